// round 11
// baseline (speedup 1.0000x reference)
#include <cuda_runtime.h>
#include <cstdint>

#define BATCH 65536

// SMEM byte offsets (phi kernel)
#define SM_A1H   0          // 64 rows x 20 words = 5120 B (layer-1 A hi, K=64)
#define SM_A1L   5120
#define SM_SAIN  10240      // 64 floats (input row scales)
#define SM_HH    10496      // h / s image hi: 64 rows x 68 words = 17408 B
#define SM_HL    27904
#define SM_WB    45312      // two weight chunk buffers, 32768 B each
#define SM_BIAS  110848     // b2[256] b5[256] w6[256] sb1[256] sb2[256] sb5[256] b6
#define SM_RMAX  117248     // 64 x 4 floats
#define SM_QBUF  118272     // 256 floats
#define SMEM_BYTES 119296

#define INV127 0.0078740157480315f

// int8 weight frag images: [mlp 2][chunk 9] x (hi 16KB | lo 16KB)
// within image: [ksx 2][nt 32][lane 32][reg 2] u32
__device__ uint8_t g_wq[2u * 9u * 32768u];
// per-column weight scales: [mlp 2][mat 3][n 256]
__device__ float g_sb[2u * 3u * 256u];
// pair inputs: [pair 3][tile 1024] x { hi 1024w | lo 1024w | sa 64w } = 2112 words
__device__ uint32_t g_ain[3u * 1024u * 2112u];

// ---------------------------------------------------------------------------
__device__ __forceinline__ uint32_t smem_u32(const void* p) {
    uint32_t a;
    asm("{ .reg .u64 t; cvta.to.shared.u64 t, %1; cvt.u32.u64 %0, t; }" : "=r"(a) : "l"(p));
    return a;
}
__device__ __forceinline__ void cp16(uint32_t saddr, const void* g) {
    asm volatile("cp.async.cg.shared.global [%0], [%1], 16;" :: "r"(saddr), "l"(g));
}
#define CP_COMMIT() asm volatile("cp.async.commit_group;" ::: "memory")
#define CP_WAIT(n)  asm volatile("cp.async.wait_group %0;" :: "n"(n) : "memory")

__device__ __forceinline__ void mma_s8(int (&d)[4], const uint32_t (&a)[4],
                                       const uint32_t (&b)[2]) {
    asm("mma.sync.aligned.m16n8k32.row.col.s32.s8.s8.s32 "
        "{%0,%1,%2,%3},{%4,%5,%6,%7},{%8,%9},{%0,%1,%2,%3};"
        : "+r"(d[0]), "+r"(d[1]), "+r"(d[2]), "+r"(d[3])
        : "r"(a[0]), "r"(a[1]), "r"(a[2]), "r"(a[3]), "r"(b[0]), "r"(b[1]));
}

__device__ __forceinline__ int clamp127(int v) {
    return v < -127 ? -127 : (v > 127 ? 127 : v);
}

// ---------------------------------------------------------------------------
// Build pair-input int8 hi/lo images + per-row scale. col54 = 1.0 -> bias row.
// ---------------------------------------------------------------------------
__global__ void build_ainp(const float* __restrict__ obs, const float* __restrict__ ag,
                           const float* __restrict__ gg,  const float* __restrict__ anch,
                           const float* __restrict__ act)
{
    const int tid = threadIdx.x;
    int b = blockIdx.x * 256 + tid;
    int tile = b >> 6, m = b & 63;

    const float* ob  = obs  + (size_t)b * 55;
    const float* an  = anch + (size_t)b * 9;
    const float* agp = ag   + (size_t)b * 9;
    const float* gp  = gg   + (size_t)b * 9;
    const float* ac  = act  + (size_t)b * 4;
    const int o1s[3] = {0, 0, 1}, o2s[3] = {1, 2, 2};
    const int js[3]  = {3, 4, 6}, ks[3]  = {5, 7, 8};

    float row[55];
    for (int p = 0; p < 3; ++p) {
        bool sel = (an[js[p]] - an[ks[p]]) >= 0.0f;
        int bit2 = sel ? js[p] : ks[p];
        int oi = sel ? o1s[p] : o2s[p];
        int oj = sel ? o2s[p] : o1s[p];
        row[0] = agp[p]; row[1] = agp[bit2];
        row[2] = gp[p];  row[3] = gp[bit2];
#pragma unroll
        for (int c = 0; c < 10; ++c) row[4 + c] = ob[c];
        row[14] = (oi == 0) ? 1.f : 0.f;
        row[15] = (oi == 1) ? 1.f : 0.f;
        row[16] = (oi == 2) ? 1.f : 0.f;
        const float* of = ob + 10 + 15 * oi;
#pragma unroll
        for (int c = 0; c < 15; ++c) row[17 + c] = of[c];
        row[32] = (oj == 0) ? 1.f : 0.f;
        row[33] = (oj == 1) ? 1.f : 0.f;
        row[34] = (oj == 2) ? 1.f : 0.f;
        const float* os = ob + 10 + 15 * oj;
#pragma unroll
        for (int c = 0; c < 15; ++c) row[35 + c] = os[c];
#pragma unroll
        for (int c = 0; c < 4; ++c) row[50 + c] = ac[c];
        row[54] = 1.0f;      // bias-row activation

        float mx = 1e-20f;
#pragma unroll
        for (int i = 0; i < 55; ++i) mx = fmaxf(mx, fabsf(row[i]));
        float qs = 127.0f / mx;

        size_t base = (size_t)(p * 1024 + tile) * 2112;
#pragma unroll
        for (int w = 0; w < 16; ++w) {
            uint32_t hw = 0, lw = 0;
#pragma unroll
            for (int bb = 0; bb < 4; ++bb) {
                int i = w * 4 + bb;
                float v = (i < 55) ? row[i] : 0.f;
                float t = v * qs;
                int q  = __float2int_rn(t);
                int ql = clamp127(__float2int_rn((t - (float)q) * 127.0f));
                hw |= (uint32_t)(q  & 0xFF) << (bb * 8);
                lw |= (uint32_t)(ql & 0xFF) << (bb * 8);
            }
            g_ain[base + m * 16 + w]        = hw;
            g_ain[base + 1024 + m * 16 + w] = lw;
        }
        ((float*)g_ain)[base + 2048 + m] = mx * INV127;   // s_a
    }
}

// ---------------------------------------------------------------------------
// Pack weights into int8 hi/lo fragment images + per-column scales.
// One thread per (mlp, mat, n). mat0 = W1 (K=55 incl bias row), mat1 = W2, mat2 = W5.
// ---------------------------------------------------------------------------
__global__ void prep_w(const float* __restrict__ w1, const float* __restrict__ b1,
                       const float* __restrict__ w2, const float* __restrict__ w5,
                       const float* __restrict__ w3, const float* __restrict__ b3,
                       const float* __restrict__ w4, const float* __restrict__ w7)
{
    int g = blockIdx.x * 256 + threadIdx.x;
    if (g >= 1536) return;
    int n = g & 255, t = g >> 8;
    int mat = t % 3, mlp = t / 3;

    const float* W; const float* Bb = nullptr; int Kf, cbase;
    if (mat == 0)      { W = mlp ? w3 : w1; Bb = mlp ? b3 : b1; Kf = 55;  cbase = 0; }
    else if (mat == 1) { W = mlp ? w4 : w2; Kf = 256; cbase = 1; }
    else               { W = mlp ? w7 : w5; Kf = 256; cbase = 5; }

    float mx = 1e-20f;
    for (int k = 0; k < Kf; ++k) {
        float v = (mat == 0 && k == 54) ? Bb[n] : W[(size_t)k * 256 + n];
        mx = fmaxf(mx, fabsf(v));
    }
    g_sb[(mlp * 3 + mat) * 256 + n] = mx * INV127;
    float qs = 127.0f / mx;

    for (int k = 0; k < Kf; ++k) {
        float v = (mat == 0 && k == 54) ? Bb[n] : W[(size_t)k * 256 + n];
        float tt = v * qs;
        int q  = __float2int_rn(tt);
        int ql = clamp127(__float2int_rn((tt - (float)q) * 127.0f));
        int chunk = cbase + (k >> 6), kl = k & 63;
        int ksx = kl >> 5, lmv = (kl & 15) >> 2, reg = (kl >> 4) & 1, byt = kl & 3;
        int lanev = ((n & 7) << 2) | lmv, nt = n >> 3;
        size_t off = (size_t)(mlp * 9 + chunk) * 32768
                   + (size_t)((((ksx * 32 + nt) * 32 + lanev) * 2 + reg) << 2) + byt;
        g_wq[off]         = (uint8_t)q;
        g_wq[off + 16384] = (uint8_t)ql;
    }
}

// ---------------------------------------------------------------------------
// Chunk-stream pipelined int8 GEMM (3 passes: hh, ah*bl, al*bh).
// Global chunk sequence: {0,1,2,3,4} x 3 pairs, then {5,6,7,8}.
// ---------------------------------------------------------------------------
__device__ __forceinline__ int seq_chunk(int k) { return (k < 15) ? (k % 5) : (k - 10); }

__device__ __forceinline__ void zero_acc2(int (&hh)[2][8][4], int (&xx)[2][8][4]) {
#pragma unroll
    for (int mt = 0; mt < 2; ++mt)
#pragma unroll
        for (int nt = 0; nt < 8; ++nt)
#pragma unroll
            for (int i = 0; i < 4; ++i) { hh[mt][nt][i] = 0; xx[mt][nt][i] = 0; }
}

__device__ __forceinline__ void stage_issue(uint32_t sb, int buf, int gchunk, int tid) {
    uint32_t dst = sb + SM_WB + buf * 32768 + tid * 16;
    const uint4* src = (const uint4*)(g_wq + (size_t)gchunk * 32768) + tid;
#pragma unroll
    for (int i = 0; i < 8; ++i)
        cp16(dst + i * 4096, src + i * 256);
    CP_COMMIT();
}

__device__ __forceinline__ void do_gemm(char* sm, uint32_t sb, int wbase, int nchunks,
                                        int& k, int imgH, int imgL, int stride,
                                        int (&hh)[2][8][4], int (&xx)[2][8][4],
                                        int tid, int lane, int warpM, int warpN)
{
    const int l4 = lane >> 2, lm = lane & 3;
    const uint32_t* AH = (const uint32_t*)(sm + imgH);
    const uint32_t* AL = (const uint32_t*)(sm + imgL);

    for (int ci = 0; ci < nchunks; ++ci, ++k) {
        if (k + 1 < 19) {
            stage_issue(sb, (k + 1) & 1, wbase + seq_chunk(k + 1), tid);
            CP_WAIT(1);
        } else {
            CP_WAIT(0);
        }
        __syncthreads();   // chunk k resident; A image writes visible

        const uint32_t* wb = (const uint32_t*)(sm + SM_WB + (k & 1) * 32768);
#pragma unroll
        for (int ksx = 0; ksx < 2; ++ksx) {
            const int k0w = ci * 16 + ksx * 8;
            uint32_t ah[2][4], al[2][4];
#pragma unroll
            for (int mt = 0; mt < 2; ++mt) {
                int base = (warpM * 32 + mt * 16 + l4) * stride + k0w + lm;
                ah[mt][0] = AH[base];               ah[mt][1] = AH[base + 8 * stride];
                ah[mt][2] = AH[base + 4];           ah[mt][3] = AH[base + 8 * stride + 4];
                al[mt][0] = AL[base];               al[mt][1] = AL[base + 8 * stride];
                al[mt][2] = AL[base + 4];           al[mt][3] = AL[base + 8 * stride + 4];
            }
            uint32_t bh[8][2], bl[8][2];
#pragma unroll
            for (int nt = 0; nt < 8; ++nt) {
                int idx = ((ksx * 32 + warpN * 8 + nt) * 32 + lane) * 2;
                bh[nt][0] = wb[idx];        bh[nt][1] = wb[idx + 1];
                bl[nt][0] = wb[4096 + idx]; bl[nt][1] = wb[4096 + idx + 1];
            }
#pragma unroll
            for (int nt = 0; nt < 8; ++nt) {
                mma_s8(hh[0][nt], ah[0], bh[nt]);
                mma_s8(hh[1][nt], ah[1], bh[nt]);
            }
#pragma unroll
            for (int nt = 0; nt < 8; ++nt) {
                mma_s8(xx[0][nt], ah[0], bl[nt]);
                mma_s8(xx[1][nt], ah[1], bl[nt]);
            }
#pragma unroll
            for (int nt = 0; nt < 8; ++nt) {
                mma_s8(xx[0][nt], al[0], bh[nt]);
                mma_s8(xx[1][nt], al[1], bh[nt]);
            }
        }
        __syncthreads();   // buffer (k&1) free for reuse at k+2
    }
}

// ---------------------------------------------------------------------------
// Fused phi + rho: one CTA = 64 batch rows x one MLP. Grid 2048 x 256 thr.
// ---------------------------------------------------------------------------
__global__ void __launch_bounds__(256, 1)
phi_kernel(const float* __restrict__ B2a, const float* __restrict__ B5a,
           const float* __restrict__ W6a, const float* __restrict__ B6a,
           const float* __restrict__ B2b, const float* __restrict__ B5b,
           const float* __restrict__ W6b, const float* __restrict__ B6b,
           float* __restrict__ outp)
{
    extern __shared__ char sm[];
    const uint32_t sb = smem_u32(sm);
    const int tid = threadIdx.x, lane = tid & 31, wid = tid >> 5;
    const int warpM = wid & 1, warpN = wid >> 1;
    const int bx = blockIdx.x, mlp = bx >> 10, tile = bx & 1023;
    const int m0 = tile * 64;
    const int l4 = lane >> 2, lm = lane & 3;

    const float* B2 = mlp ? B2b : B2a;
    const float* B5 = mlp ? B5b : B5a;
    const float* W6 = mlp ? W6b : W6a;
    const float* B6 = mlp ? B6b : B6a;

    float* bias = (float*)(sm + SM_BIAS);      // [0]b2 [256]b5 [512]w6 [768]sb1 [1024]sb2 [1280]sb5 [1536]b6
    float* sain = (float*)(sm + SM_SAIN);
    float* rmax = (float*)(sm + SM_RMAX);
    float* qb   = (float*)(sm + SM_QBUF);

    const int wbase = mlp * 9;
    int k = 0;
    stage_issue(sb, 0, wbase + 0, tid);        // chunk 0 prefetch overlaps setup

    bias[tid]        = B2[tid];
    bias[256 + tid]  = B5[tid];
    bias[512 + tid]  = W6[tid];
    bias[768 + tid]  = g_sb[(mlp * 3 + 0) * 256 + tid];
    bias[1024 + tid] = g_sb[(mlp * 3 + 1) * 256 + tid];
    bias[1280 + tid] = g_sb[(mlp * 3 + 2) * 256 + tid];
    if (tid == 0) bias[1536] = B6[0];

    int hh[2][8][4], xx[2][8][4];
    float sreg[2][8][4];
#pragma unroll
    for (int mt = 0; mt < 2; ++mt)
#pragma unroll
        for (int nt = 0; nt < 8; ++nt)
#pragma unroll
            for (int i = 0; i < 4; ++i) sreg[mt][nt][i] = 0.f;

    float sah[2][2];   // h row scales (dequant), persists pair-scoped

    for (int p = 0; p < 3; ++p) {
        // ---- stage layer-1 A images (stride 20 words) + row scales ----
        {
            size_t base = (size_t)(p * 1024 + tile) * 2112;
            uint32_t* dH = (uint32_t*)(sm + SM_A1H);
            uint32_t* dL = (uint32_t*)(sm + SM_A1L);
#pragma unroll
            for (int i = 0; i < 4; ++i) {
                int idx = tid + i * 256;
                int r = idx >> 4, c = idx & 15;
                dH[r * 20 + c] = g_ain[base + idx];
                dL[r * 20 + c] = g_ain[base + 1024 + idx];
            }
            if (tid < 64) sain[tid] = ((float*)g_ain)[base + 2048 + tid];
        }

        // ---- layer 1: inp @ W1 (+b1 via bias row) ----
        zero_acc2(hh, xx);
        do_gemm(sm, sb, wbase, 1, k, SM_A1H, SM_A1L, 20, hh, xx, tid, lane, warpM, warpN);

        // ---- epilogue 1: h = relu(dequant), row-max, quantize into HH/HL ----
        {
            float sa0[2][2];
#pragma unroll
            for (int mt = 0; mt < 2; ++mt) {
                int r0 = warpM * 32 + mt * 16 + l4;
                sa0[mt][0] = sain[r0]; sa0[mt][1] = sain[r0 + 8];
            }
            float rm[2][2] = {{0.f, 0.f}, {0.f, 0.f}};
#pragma unroll
            for (int mt = 0; mt < 2; ++mt)
#pragma unroll
                for (int nt = 0; nt < 8; ++nt) {
                    int c = warpN * 64 + nt * 8 + lm * 2;
                    float s0 = bias[768 + c], s1 = bias[768 + c + 1];
                    float x0 = ((float)hh[mt][nt][0] + (float)xx[mt][nt][0] * INV127) * sa0[mt][0] * s0;
                    float x1 = ((float)hh[mt][nt][1] + (float)xx[mt][nt][1] * INV127) * sa0[mt][0] * s1;
                    float x2 = ((float)hh[mt][nt][2] + (float)xx[mt][nt][2] * INV127) * sa0[mt][1] * s0;
                    float x3 = ((float)hh[mt][nt][3] + (float)xx[mt][nt][3] * INV127) * sa0[mt][1] * s1;
                    rm[mt][0] = fmaxf(rm[mt][0], fmaxf(fmaxf(x0, 0.f), fmaxf(x1, 0.f)));
                    rm[mt][1] = fmaxf(rm[mt][1], fmaxf(fmaxf(x2, 0.f), fmaxf(x3, 0.f)));
                }
#pragma unroll
            for (int mt = 0; mt < 2; ++mt)
#pragma unroll
                for (int h2 = 0; h2 < 2; ++h2) {
                    float v = rm[mt][h2];
                    v = fmaxf(v, __shfl_xor_sync(0xffffffffu, v, 1));
                    v = fmaxf(v, __shfl_xor_sync(0xffffffffu, v, 2));
                    if (lm == 0) rmax[(warpM * 32 + mt * 16 + h2 * 8 + l4) * 4 + warpN] = v;
                }
            __syncthreads();
            float qsh[2][2];
#pragma unroll
            for (int mt = 0; mt < 2; ++mt)
#pragma unroll
                for (int h2 = 0; h2 < 2; ++h2) {
                    int r = warpM * 32 + mt * 16 + h2 * 8 + l4;
                    float4 f = *(float4*)&rmax[r * 4];
                    float mxr = fmaxf(fmaxf(f.x, f.y), fmaxf(f.z, f.w));
                    mxr = fmaxf(mxr, 1e-20f);
                    sah[mt][h2] = mxr * INV127;
                    qsh[mt][h2] = 127.0f / mxr;
                }
#pragma unroll
            for (int mt = 0; mt < 2; ++mt)
#pragma unroll
                for (int nt = 0; nt < 8; ++nt) {
                    int c = warpN * 64 + nt * 8 + lm * 2;
                    float s0 = bias[768 + c], s1 = bias[768 + c + 1];
                    int r0 = warpM * 32 + mt * 16 + l4;
#pragma unroll
                    for (int h2 = 0; h2 < 2; ++h2) {
                        float y0 = fmaxf(((float)hh[mt][nt][2 * h2]     + (float)xx[mt][nt][2 * h2]     * INV127) * sa0[mt][h2] * s0, 0.f);
                        float y1 = fmaxf(((float)hh[mt][nt][2 * h2 + 1] + (float)xx[mt][nt][2 * h2 + 1] * INV127) * sa0[mt][h2] * s1, 0.f);
                        float t0 = y0 * qsh[mt][h2], t1 = y1 * qsh[mt][h2];
                        int q0 = __float2int_rn(t0), q1 = __float2int_rn(t1);
                        int l0 = clamp127(__float2int_rn((t0 - (float)q0) * 127.0f));
                        int l1 = clamp127(__float2int_rn((t1 - (float)q1) * 127.0f));
                        int r = r0 + h2 * 8;
                        *(uint16_t*)(sm + SM_HH + r * 272 + c) =
                            (uint16_t)((q0 & 0xFF) | ((q1 & 0xFF) << 8));
                        *(uint16_t*)(sm + SM_HL + r * 272 + c) =
                            (uint16_t)((l0 & 0xFF) | ((l1 & 0xFF) << 8));
                    }
                }
        }

        // ---- layer 2: h @ W2 ----
        zero_acc2(hh, xx);
        do_gemm(sm, sb, wbase, 4, k, SM_HH, SM_HL, 68, hh, xx, tid, lane, warpM, warpN);

        // ---- epilogue 2: sreg += relu(dequant + b2) ----
#pragma unroll
        for (int mt = 0; mt < 2; ++mt)
#pragma unroll
            for (int nt = 0; nt < 8; ++nt) {
                int c = warpN * 64 + nt * 8 + lm * 2;
                float s0 = bias[1024 + c], s1 = bias[1024 + c + 1];
                float b0 = bias[c], b1v = bias[c + 1];
                sreg[mt][nt][0] += fmaxf(((float)hh[mt][nt][0] + (float)xx[mt][nt][0] * INV127) * sah[mt][0] * s0 + b0, 0.f);
                sreg[mt][nt][1] += fmaxf(((float)hh[mt][nt][1] + (float)xx[mt][nt][1] * INV127) * sah[mt][0] * s1 + b1v, 0.f);
                sreg[mt][nt][2] += fmaxf(((float)hh[mt][nt][2] + (float)xx[mt][nt][2] * INV127) * sah[mt][1] * s0 + b0, 0.f);
                sreg[mt][nt][3] += fmaxf(((float)hh[mt][nt][3] + (float)xx[mt][nt][3] * INV127) * sah[mt][1] * s1 + b1v, 0.f);
            }
    }

    // ---- quantize s (register fragments) into HH/HL for rho ----
    {
        float rm[2][2] = {{0.f, 0.f}, {0.f, 0.f}};
#pragma unroll
        for (int mt = 0; mt < 2; ++mt)
#pragma unroll
            for (int nt = 0; nt < 8; ++nt) {
                rm[mt][0] = fmaxf(rm[mt][0], fmaxf(sreg[mt][nt][0], sreg[mt][nt][1]));
                rm[mt][1] = fmaxf(rm[mt][1], fmaxf(sreg[mt][nt][2], sreg[mt][nt][3]));
            }
        __syncthreads();   // rmax buffer free (prior epilogue-1 readers done)
#pragma unroll
        for (int mt = 0; mt < 2; ++mt)
#pragma unroll
            for (int h2 = 0; h2 < 2; ++h2) {
                float v = rm[mt][h2];
                v = fmaxf(v, __shfl_xor_sync(0xffffffffu, v, 1));
                v = fmaxf(v, __shfl_xor_sync(0xffffffffu, v, 2));
                if (lm == 0) rmax[(warpM * 32 + mt * 16 + h2 * 8 + l4) * 4 + warpN] = v;
            }
        __syncthreads();
        float qss[2][2];
#pragma unroll
        for (int mt = 0; mt < 2; ++mt)
#pragma unroll
            for (int h2 = 0; h2 < 2; ++h2) {
                int r = warpM * 32 + mt * 16 + h2 * 8 + l4;
                float4 f = *(float4*)&rmax[r * 4];
                float mxr = fmaxf(fmaxf(f.x, f.y), fmaxf(f.z, f.w));
                mxr = fmaxf(mxr, 1e-20f);
                sah[mt][h2] = mxr * INV127;       // reuse sah as s-scale
                qss[mt][h2] = 127.0f / mxr;
            }
#pragma unroll
        for (int mt = 0; mt < 2; ++mt)
#pragma unroll
            for (int nt = 0; nt < 8; ++nt) {
                int c = warpN * 64 + nt * 8 + lm * 2;
                int r0 = warpM * 32 + mt * 16 + l4;
#pragma unroll
                for (int h2 = 0; h2 < 2; ++h2) {
                    float t0 = sreg[mt][nt][2 * h2]     * qss[mt][h2];
                    float t1 = sreg[mt][nt][2 * h2 + 1] * qss[mt][h2];
                    int q0 = __float2int_rn(t0), q1 = __float2int_rn(t1);
                    int l0 = clamp127(__float2int_rn((t0 - (float)q0) * 127.0f));
                    int l1 = clamp127(__float2int_rn((t1 - (float)q1) * 127.0f));
                    int r = r0 + h2 * 8;
                    *(uint16_t*)(sm + SM_HH + r * 272 + c) =
                        (uint16_t)((q0 & 0xFF) | ((q1 & 0xFF) << 8));
                    *(uint16_t*)(sm + SM_HL + r * 272 + c) =
                        (uint16_t)((l0 & 0xFF) | ((l1 & 0xFF) << 8));
                }
            }
    }

    // ---- rho: s @ W5 ----
    zero_acc2(hh, xx);
    do_gemm(sm, sb, wbase, 4, k, SM_HH, SM_HL, 68, hh, xx, tid, lane, warpM, warpN);

    // ---- rho epilogue: q = relu(dequant + b5) . w6, reduce ----
#pragma unroll
    for (int mt = 0; mt < 2; ++mt) {
        float s0a = 0.f, s1a = 0.f;
#pragma unroll
        for (int nt = 0; nt < 8; ++nt) {
            int c = warpN * 64 + nt * 8 + lm * 2;
            float sc0 = bias[1280 + c], sc1 = bias[1280 + c + 1];
            float b5c0 = bias[256 + c], b5c1 = bias[256 + c + 1];
            float w6c0 = bias[512 + c], w6c1 = bias[512 + c + 1];
            s0a += fmaxf(((float)hh[mt][nt][0] + (float)xx[mt][nt][0] * INV127) * sah[mt][0] * sc0 + b5c0, 0.f) * w6c0
                 + fmaxf(((float)hh[mt][nt][1] + (float)xx[mt][nt][1] * INV127) * sah[mt][0] * sc1 + b5c1, 0.f) * w6c1;
            s1a += fmaxf(((float)hh[mt][nt][2] + (float)xx[mt][nt][2] * INV127) * sah[mt][1] * sc0 + b5c0, 0.f) * w6c0
                 + fmaxf(((float)hh[mt][nt][3] + (float)xx[mt][nt][3] * INV127) * sah[mt][1] * sc1 + b5c1, 0.f) * w6c1;
        }
        s0a += __shfl_xor_sync(0xffffffffu, s0a, 1);
        s0a += __shfl_xor_sync(0xffffffffu, s0a, 2);
        s1a += __shfl_xor_sync(0xffffffffu, s1a, 1);
        s1a += __shfl_xor_sync(0xffffffffu, s1a, 2);
        if (lm == 0) {
            int r0 = warpM * 32 + mt * 16 + l4;
            qb[r0 * 4 + warpN] = s0a;
            qb[(r0 + 8) * 4 + warpN] = s1a;
        }
    }
    __syncthreads();
    if (tid < 64)
        outp[(size_t)mlp * BATCH + m0 + tid] =
            qb[tid * 4] + qb[tid * 4 + 1] + qb[tid * 4 + 2] + qb[tid * 4 + 3] + bias[1536];
}

// ---------------------------------------------------------------------------
extern "C" void kernel_launch(void* const* d_in, const int* in_sizes, int n_in,
                              void* d_out, int out_size)
{
    const float* obs    = (const float*)d_in[0];
    const float* ag     = (const float*)d_in[1];
    const float* gg     = (const float*)d_in[2];
    const float* anchor = (const float*)d_in[3];
    const float* act    = (const float*)d_in[4];
    const float* w1 = (const float*)d_in[5];  const float* b1 = (const float*)d_in[6];
    const float* w2 = (const float*)d_in[7];  const float* b2 = (const float*)d_in[8];
    const float* w3 = (const float*)d_in[9];  const float* b3 = (const float*)d_in[10];
    const float* w4 = (const float*)d_in[11]; const float* b4 = (const float*)d_in[12];
    const float* w5 = (const float*)d_in[13]; const float* b5 = (const float*)d_in[14];
    const float* w6 = (const float*)d_in[15]; const float* b6 = (const float*)d_in[16];
    const float* w7 = (const float*)d_in[17]; const float* b7 = (const float*)d_in[18];
    const float* w8 = (const float*)d_in[19]; const float* b8 = (const float*)d_in[20];
    float* out = (float*)d_out;

    cudaFuncSetAttribute(phi_kernel, cudaFuncAttributeMaxDynamicSharedMemorySize, SMEM_BYTES);

    build_ainp<<<BATCH / 256, 256>>>(obs, ag, gg, anchor, act);
    prep_w<<<6, 256>>>(w1, b1, w2, w5, w3, b3, w4, w7);
    phi_kernel<<<2048, 256, SMEM_BYTES>>>(b2, b5, w6, b6, b4, b7, w8, b8, out);
}

// round 12
// speedup vs baseline: 3.0353x; 3.0353x over previous
#include <cuda_runtime.h>
#include <cuda_bf16.h>
#include <cstdint>

#define BATCH 65536
#define THREADS 512

// SMEM byte offsets (phi kernel)
#define SM_AHI  0            // 64 rows x 132 words = 33792 B
#define SM_ALO  33792
#define SM_WB   67584        // two weight chunk buffers, 65536 B each
#define SM_BIAS 198656       // b2[256] b5[256] w6[256] b6[1]
#define SM_QBUF 201744       // 64 x 4 fp32
#define SMEM_BYTES 202768

// weight fragment images: [mlp 2][chunk 9][hl 2][ks 4][nt 32][lane 32][2] u32
__device__ uint32_t g_wf[2u * 9u * 2u * 8192u];
// pair-input images: [pair 3][tile 1024][hl 2][2048] u32 (64 rows x 32 words)
__device__ uint32_t g_ainp[3u * 1024u * 2u * 2048u];

// ---------------------------------------------------------------------------
__device__ __forceinline__ uint32_t smem_u32(const void* p) {
    uint32_t a;
    asm("{ .reg .u64 t; cvta.to.shared.u64 t, %1; cvt.u32.u64 %0, t; }" : "=r"(a) : "l"(p));
    return a;
}
__device__ __forceinline__ void cp16(uint32_t saddr, const void* g) {
    asm volatile("cp.async.cg.shared.global [%0], [%1], 16;" :: "r"(saddr), "l"(g));
}
#define CP_COMMIT() asm volatile("cp.async.commit_group;" ::: "memory")
#define CP_WAIT(n)  asm volatile("cp.async.wait_group %0;" :: "n"(n) : "memory")

__device__ __forceinline__ void split2(float a, float b, uint32_t& hi, uint32_t& lo) {
    __nv_bfloat16 h0 = __float2bfloat16_rn(a), h1 = __float2bfloat16_rn(b);
    float l0 = a - __bfloat162float(h0), l1 = b - __bfloat162float(h1);
    __nv_bfloat162 hh = __halves2bfloat162(h0, h1);
    __nv_bfloat162 ll = __halves2bfloat162(__float2bfloat16_rn(l0), __float2bfloat16_rn(l1));
    hi = *(uint32_t*)&hh; lo = *(uint32_t*)&ll;
}

__device__ __forceinline__ void mma_bf16(float (&d)[4], const uint32_t (&a)[4],
                                         const uint32_t (&b)[2]) {
    asm("mma.sync.aligned.m16n8k16.row.col.f32.bf16.bf16.f32 "
        "{%0,%1,%2,%3},{%4,%5,%6,%7},{%8,%9},{%0,%1,%2,%3};"
        : "+f"(d[0]), "+f"(d[1]), "+f"(d[2]), "+f"(d[3])
        : "r"(a[0]), "r"(a[1]), "r"(a[2]), "r"(a[3]), "r"(b[0]), "r"(b[1]));
}

// ---------------------------------------------------------------------------
// Build pair-input bf16 hi/lo images. SMEM-staged for coalesced global writes.
// Block = 256 samples = 4 tiles. col 54 = 1.0 activates W1's bias row.
// ---------------------------------------------------------------------------
__global__ void build_ainp(const float* __restrict__ obs, const float* __restrict__ ag,
                           const float* __restrict__ gg,  const float* __restrict__ anch,
                           const float* __restrict__ act)
{
    extern __shared__ uint32_t sbuf[];          // [2][256 * 33] words, stride 33
    const int tid = threadIdx.x;
    int b = blockIdx.x * 256 + tid;
    int T0 = blockIdx.x * 4;

    const float* ob  = obs  + (size_t)b * 55;
    const float* an  = anch + (size_t)b * 9;
    const float* agp = ag   + (size_t)b * 9;
    const float* gp  = gg   + (size_t)b * 9;
    const float* ac  = act  + (size_t)b * 4;
    const int o1s[3] = {0, 0, 1}, o2s[3] = {1, 2, 2};
    const int js[3]  = {3, 4, 6}, ks[3]  = {5, 7, 8};

    float row[64];
    for (int p = 0; p < 3; ++p) {
        bool sel = (an[js[p]] - an[ks[p]]) >= 0.0f;
        int bit2 = sel ? js[p] : ks[p];
        int oi = sel ? o1s[p] : o2s[p];
        int oj = sel ? o2s[p] : o1s[p];
        row[0] = agp[p]; row[1] = agp[bit2];
        row[2] = gp[p];  row[3] = gp[bit2];
#pragma unroll
        for (int c = 0; c < 10; ++c) row[4 + c] = ob[c];
        row[14] = (oi == 0) ? 1.f : 0.f;
        row[15] = (oi == 1) ? 1.f : 0.f;
        row[16] = (oi == 2) ? 1.f : 0.f;
        const float* of = ob + 10 + 15 * oi;
#pragma unroll
        for (int c = 0; c < 15; ++c) row[17 + c] = of[c];
        row[32] = (oj == 0) ? 1.f : 0.f;
        row[33] = (oj == 1) ? 1.f : 0.f;
        row[34] = (oj == 2) ? 1.f : 0.f;
        const float* os = ob + 10 + 15 * oj;
#pragma unroll
        for (int c = 0; c < 15; ++c) row[35 + c] = os[c];
#pragma unroll
        for (int c = 0; c < 4; ++c) row[50 + c] = ac[c];
        row[54] = 1.0f;
#pragma unroll
        for (int c = 55; c < 64; ++c) row[c] = 0.f;

        __syncthreads();   // previous pair's copy-out done
        uint32_t* sH = sbuf + (size_t)tid * 33;
        uint32_t* sL = sbuf + 256 * 33 + (size_t)tid * 33;
#pragma unroll
        for (int i = 0; i < 32; ++i) {
            uint32_t hi, lo;
            split2(row[2 * i], row[2 * i + 1], hi, lo);
            sH[i] = hi; sL[i] = lo;
        }
        __syncthreads();

        // coalesced copy-out: 16384 words -> g_ainp[p][T0..T0+3][hl][2048]
#pragma unroll
        for (int i = 0; i < 64; ++i) {
            int f = tid + i * 256;
            int h = f >> 13, r = f & 8191;
            int t = r >> 11, m = (r & 2047) >> 5, w = r & 31;
            uint32_t v = sbuf[h * (256 * 33) + (t * 64 + m) * 33 + w];
            g_ainp[(size_t)((p * 1024 + T0 + t) * 2 + h) * 2048 + (r & 2047)] = v;
        }
    }
}

// ---------------------------------------------------------------------------
// Pack weights (+bias row) into per-lane B-fragment hi/lo images
// ---------------------------------------------------------------------------
__global__ void prep_w(const float* __restrict__ w1, const float* __restrict__ b1,
                       const float* __restrict__ w2, const float* __restrict__ w5,
                       const float* __restrict__ w3, const float* __restrict__ b3,
                       const float* __restrict__ w4, const float* __restrict__ w7)
{
    int gid = blockIdx.x * 256 + threadIdx.x;          // 73728
    int lane = gid & 31, nt = (gid >> 5) & 31, ksx = (gid >> 10) & 3;
    int mc = gid >> 12, chunk = mc % 9, mlp = mc / 9;

    const float* W; const float* Bb = nullptr; int k0 = 0, Kmax = 256;
    if (mlp == 0) {
        if (chunk == 0)     { W = w1; Bb = b1; Kmax = 54; }
        else if (chunk < 5) { W = w2; k0 = (chunk - 1) * 64; }
        else                { W = w5; k0 = (chunk - 5) * 64; }
    } else {
        if (chunk == 0)     { W = w3; Bb = b3; Kmax = 54; }
        else if (chunk < 5) { W = w4; k0 = (chunk - 1) * 64; }
        else                { W = w7; k0 = (chunk - 5) * 64; }
    }

    int n = nt * 8 + (lane >> 2);
    size_t baseH = ((size_t)((mlp * 9 + chunk) * 2 + 0) * 4 + ksx) * 2048 + (size_t)nt * 64 + lane * 2;
    size_t baseL = ((size_t)((mlp * 9 + chunk) * 2 + 1) * 4 + ksx) * 2048 + (size_t)nt * 64 + lane * 2;
#pragma unroll
    for (int j = 0; j < 2; ++j) {
        int k = k0 + ksx * 16 + (lane & 3) * 2 + j * 8;
        float v0 = 0.f, v1 = 0.f;
        if (k < Kmax)               v0 = W[(size_t)k * 256 + n];
        else if (Bb && k == 54)     v0 = Bb[n];
        if (k + 1 < Kmax)           v1 = W[(size_t)(k + 1) * 256 + n];
        else if (Bb && k + 1 == 54) v1 = Bb[n];
        uint32_t hi, lo;
        split2(v0, v1, hi, lo);
        g_wf[baseH + j] = hi;
        g_wf[baseL + j] = lo;
    }
}

// ---------------------------------------------------------------------------
// Chunk-stream pipelined GEMM (bf16 x3 split), 16 warps, warp tile 16x64.
// Global chunk sequence: seq[k] = k%5 for k<15, k-10 for k>=15.
// ---------------------------------------------------------------------------
__device__ __forceinline__ int seq_chunk(int k) { return (k < 15) ? (k % 5) : (k - 10); }

__device__ __forceinline__ void zero_acc(float (&acc)[8][4]) {
#pragma unroll
    for (int nt = 0; nt < 8; ++nt)
#pragma unroll
        for (int i = 0; i < 4; ++i) acc[nt][i] = 0.f;
}

__device__ __forceinline__ void stage_issue(uint32_t sb, int buf, int gchunk, int tid) {
    uint32_t dst = sb + SM_WB + buf * 65536 + tid * 16;
    const uint4* src = (const uint4*)g_wf + (size_t)gchunk * 4096 + tid;
#pragma unroll
    for (int i = 0; i < 8; ++i)
        cp16(dst + i * 8192, src + i * 512);
    CP_COMMIT();
}

__device__ __forceinline__ void do_gemm(char* sm, uint32_t sb, int wbase, int nchunks,
                                        int& k, float (&acc)[8][4],
                                        int tid, int lane, int warpM, int warpN)
{
    const int l4 = lane >> 2, lm = lane & 3;
    const uint32_t* AH = (const uint32_t*)(sm + SM_AHI);
    const uint32_t* AL = (const uint32_t*)(sm + SM_ALO);

    for (int ci = 0; ci < nchunks; ++ci, ++k) {
        if (k + 1 < 19) {
            stage_issue(sb, (k + 1) & 1, wbase + seq_chunk(k + 1), tid);
            CP_WAIT(1);
        } else {
            CP_WAIT(0);
        }
        __syncthreads();   // chunk k resident for all warps; A images visible

        const uint32_t* wb = (const uint32_t*)(sm + SM_WB + (k & 1) * 65536);
        const int akw = ci * 32;
#pragma unroll
        for (int ksx = 0; ksx < 4; ++ksx) {
            uint32_t ah[4], al[4];
            {
                int w0 = (warpM * 16 + l4) * 132 + akw + ksx * 8 + lm;
                ah[0] = AH[w0];        ah[1] = AH[w0 + 8 * 132];
                ah[2] = AH[w0 + 4];    ah[3] = AH[w0 + 8 * 132 + 4];
                al[0] = AL[w0];        al[1] = AL[w0 + 8 * 132];
                al[2] = AL[w0 + 4];    al[3] = AL[w0 + 8 * 132 + 4];
            }
            uint32_t b0[8][2];
#pragma unroll
            for (int nt = 0; nt < 8; ++nt) {
                int idx = (ksx * 32 + warpN * 8 + nt) * 64 + lane * 2;
                b0[nt][0] = wb[idx]; b0[nt][1] = wb[idx + 1];
            }
#pragma unroll
            for (int nt = 0; nt < 8; ++nt)
                mma_bf16(acc[nt], ah, b0[nt]);
#pragma unroll
            for (int nt = 0; nt < 8; ++nt)
                mma_bf16(acc[nt], al, b0[nt]);
#pragma unroll
            for (int nt = 0; nt < 8; ++nt) {
                int idx = 8192 + (ksx * 32 + warpN * 8 + nt) * 64 + lane * 2;
                uint32_t bl[2] = { wb[idx], wb[idx + 1] };
                mma_bf16(acc[nt], ah, bl);
            }
        }
        __syncthreads();   // compute done; buffer (k&1) free for reuse at k+2
    }
}

// ---------------------------------------------------------------------------
// Fused phi + rho: one CTA = 64 batch rows x one MLP. Grid 2048 x 512 thr.
// 16 warps: warpM = wid&3 (16-row slices), warpN = wid>>2 (64-col slices).
// ---------------------------------------------------------------------------
__global__ void __launch_bounds__(THREADS, 1)
phi_kernel(const float* __restrict__ B2a, const float* __restrict__ B5a,
           const float* __restrict__ W6a, const float* __restrict__ B6a,
           const float* __restrict__ B2b, const float* __restrict__ B5b,
           const float* __restrict__ W6b, const float* __restrict__ B6b,
           float* __restrict__ outp)
{
    extern __shared__ char sm[];
    const uint32_t sb = smem_u32(sm);
    const int tid = threadIdx.x, lane = tid & 31, wid = tid >> 5;
    const int warpM = wid & 3, warpN = wid >> 2;
    const int bx = blockIdx.x, mlp = bx >> 10, tile = bx & 1023;
    const int m0 = tile * 64;
    const int l4 = lane >> 2, lm = lane & 3;

    const float* B2 = mlp ? B2b : B2a;
    const float* B5 = mlp ? B5b : B5a;
    const float* W6 = mlp ? W6b : W6a;
    const float* B6 = mlp ? B6b : B6a;

    float* bias = (float*)(sm + SM_BIAS);
    float* qb   = (float*)(sm + SM_QBUF);

    const int wbase = mlp * 9;
    int k = 0;
    // prefetch chunk 0 immediately; overlaps bias + A-image staging below
    stage_issue(sb, 0, wbase + 0, tid);

    if (tid < 256) {
        bias[tid] = B2[tid]; bias[256 + tid] = B5[tid]; bias[512 + tid] = W6[tid];
        if (tid == 0) bias[768] = B6[0];
    }

    float acc[8][4];
    float sreg[8][4];
#pragma unroll
    for (int nt = 0; nt < 8; ++nt)
#pragma unroll
        for (int i = 0; i < 4; ++i) sreg[nt][i] = 0.f;

    for (int p = 0; p < 3; ++p) {
        // stage pair-input images (hi/lo) into A buffers, row stride 132 words
#pragma unroll
        for (int hl = 0; hl < 2; ++hl) {
            const uint4* src = (const uint4*)(g_ainp + (size_t)((p * 1024 + tile) * 2 + hl) * 2048);
            char* dbase = sm + (hl ? SM_ALO : SM_AHI);
            int row = tid >> 3, cw4 = tid & 7;
            *(uint4*)(dbase + (row * 132 + cw4 * 4) * 4) = src[tid];
        }

        // ---- layer 1: acc = inp @ W1 (+b1 via bias row) ----
        zero_acc(acc);
        do_gemm(sm, sb, wbase, 1, k, acc, tid, lane, warpM, warpN);

        // epilogue 1: h = relu(acc) -> split -> A images
        {
            int r0 = warpM * 16 + l4;
#pragma unroll
            for (int nt = 0; nt < 8; ++nt) {
                int cw = warpN * 32 + nt * 4 + lm;
                uint32_t hi, lo;
                split2(fmaxf(acc[nt][0], 0.f), fmaxf(acc[nt][1], 0.f), hi, lo);
                *(uint32_t*)(sm + SM_AHI + (r0 * 132 + cw) * 4) = hi;
                *(uint32_t*)(sm + SM_ALO + (r0 * 132 + cw) * 4) = lo;
                split2(fmaxf(acc[nt][2], 0.f), fmaxf(acc[nt][3], 0.f), hi, lo);
                *(uint32_t*)(sm + SM_AHI + ((r0 + 8) * 132 + cw) * 4) = hi;
                *(uint32_t*)(sm + SM_ALO + ((r0 + 8) * 132 + cw) * 4) = lo;
            }
        }

        // ---- layer 2: acc = h @ W2 ----
        zero_acc(acc);
        do_gemm(sm, sb, wbase, 4, k, acc, tid, lane, warpM, warpN);

        // epilogue 2 (registers): sreg += relu(acc + b2)
#pragma unroll
        for (int nt = 0; nt < 8; ++nt) {
            int col = warpN * 64 + nt * 8 + lm * 2;
            sreg[nt][0] += fmaxf(acc[nt][0] + bias[col], 0.f);
            sreg[nt][1] += fmaxf(acc[nt][1] + bias[col + 1], 0.f);
            sreg[nt][2] += fmaxf(acc[nt][2] + bias[col], 0.f);
            sreg[nt][3] += fmaxf(acc[nt][3] + bias[col + 1], 0.f);
        }
    }

    // s (register fragments) -> split A images
    {
        int r0 = warpM * 16 + l4;
#pragma unroll
        for (int nt = 0; nt < 8; ++nt) {
            int cw = warpN * 32 + nt * 4 + lm;
            uint32_t hi, lo;
            split2(sreg[nt][0], sreg[nt][1], hi, lo);
            *(uint32_t*)(sm + SM_AHI + (r0 * 132 + cw) * 4) = hi;
            *(uint32_t*)(sm + SM_ALO + (r0 * 132 + cw) * 4) = lo;
            split2(sreg[nt][2], sreg[nt][3], hi, lo);
            *(uint32_t*)(sm + SM_AHI + ((r0 + 8) * 132 + cw) * 4) = hi;
            *(uint32_t*)(sm + SM_ALO + ((r0 + 8) * 132 + cw) * 4) = lo;
        }
    }

    // ---- rho: acc = s @ W5 ----
    zero_acc(acc);
    do_gemm(sm, sb, wbase, 4, k, acc, tid, lane, warpM, warpN);

    // rho epilogue: q = relu(acc + b5) . w6, reduce
    {
        float s0 = 0.f, s1 = 0.f;
#pragma unroll
        for (int nt = 0; nt < 8; ++nt) {
            int col = warpN * 64 + nt * 8 + lm * 2;
            float b5c0 = bias[256 + col], b5c1 = bias[256 + col + 1];
            float w6c0 = bias[512 + col], w6c1 = bias[512 + col + 1];
            s0 += fmaxf(acc[nt][0] + b5c0, 0.f) * w6c0
                + fmaxf(acc[nt][1] + b5c1, 0.f) * w6c1;
            s1 += fmaxf(acc[nt][2] + b5c0, 0.f) * w6c0
                + fmaxf(acc[nt][3] + b5c1, 0.f) * w6c1;
        }
        s0 += __shfl_xor_sync(0xffffffffu, s0, 1);
        s0 += __shfl_xor_sync(0xffffffffu, s0, 2);
        s1 += __shfl_xor_sync(0xffffffffu, s1, 1);
        s1 += __shfl_xor_sync(0xffffffffu, s1, 2);
        if (lm == 0) {
            int r0 = warpM * 16 + l4;
            qb[r0 * 4 + warpN] = s0;
            qb[(r0 + 8) * 4 + warpN] = s1;
        }
    }
    __syncthreads();
    if (tid < 64)
        outp[(size_t)mlp * BATCH + m0 + tid] =
            qb[tid * 4] + qb[tid * 4 + 1] + qb[tid * 4 + 2] + qb[tid * 4 + 3] + bias[768];
}

// ---------------------------------------------------------------------------
extern "C" void kernel_launch(void* const* d_in, const int* in_sizes, int n_in,
                              void* d_out, int out_size)
{
    const float* obs    = (const float*)d_in[0];
    const float* ag     = (const float*)d_in[1];
    const float* gg     = (const float*)d_in[2];
    const float* anchor = (const float*)d_in[3];
    const float* act    = (const float*)d_in[4];
    const float* w1 = (const float*)d_in[5];  const float* b1 = (const float*)d_in[6];
    const float* w2 = (const float*)d_in[7];  const float* b2 = (const float*)d_in[8];
    const float* w3 = (const float*)d_in[9];  const float* b3 = (const float*)d_in[10];
    const float* w4 = (const float*)d_in[11]; const float* b4 = (const float*)d_in[12];
    const float* w5 = (const float*)d_in[13]; const float* b5 = (const float*)d_in[14];
    const float* w6 = (const float*)d_in[15]; const float* b6 = (const float*)d_in[16];
    const float* w7 = (const float*)d_in[17]; const float* b7 = (const float*)d_in[18];
    const float* w8 = (const float*)d_in[19]; const float* b8 = (const float*)d_in[20];
    float* out = (float*)d_out;

    cudaFuncSetAttribute(phi_kernel, cudaFuncAttributeMaxDynamicSharedMemorySize, SMEM_BYTES);
    cudaFuncSetAttribute(build_ainp, cudaFuncAttributeMaxDynamicSharedMemorySize, 67584);

    build_ainp<<<BATCH / 256, 256, 67584>>>(obs, ag, gg, anchor, act);
    prep_w<<<288, 256>>>(w1, b1, w2, w5, w3, b3, w4, w7);
    phi_kernel<<<2048, THREADS, SMEM_BYTES>>>(b2, b5, w6, b6, b4, b7, w8, b8, out);
}